// round 12
// baseline (speedup 1.0000x reference)
#include <cuda_runtime.h>
#include <cuda_fp16.h>
#include <cstdint>

// ---------------------------------------------------------------------------
// FixedTopKLoRALinear: out = x@W^T + bias + softtopk(x@A^T)@B^T
// x[8192,4096], A[64,4096], B[4096,64], W[4096,4096], bias[4096]
//
// fp16 m16n8k16 mma.sync, fp32 accum (fp16 mantissa == tf32 mantissa).
// Main GEMM: 128x256 CTA tile, 8 warps (2m x 4n), warp tile 64x64,
// 3-stage cp.async pipeline, ldmatrix.x4 fragment loads, pitch-36 smem.
// LoRA fused as one extra K-tile (R=64). tcgen05 unavailable (plain sm_103).
// ---------------------------------------------------------------------------

#define D_IN_C   4096
#define D_IN_P   2048          // fp16 pairs per x/W/A row
#define N_FIX    4096
#define R_C      64
#define R_P      32            // fp16 pairs per zs/B row
#define KSEL_C   16
#define TEMP_C   0.1f
#define MAX_M    8192

#define PITCH    36            // uint32 words per smem row

// Scratch (allocation-free: device globals)
__device__ uint32_t g_xh [MAX_M * D_IN_P];
__device__ uint32_t g_wh [N_FIX * D_IN_P];
__device__ uint32_t g_ah [R_C   * D_IN_P];
__device__ uint32_t g_bh [N_FIX * R_P];
__device__ float    g_z  [MAX_M * R_C];
__device__ uint32_t g_zsh[MAX_M * R_P];

// ---------------------------------------------------------------------------
__device__ __forceinline__ uint32_t pack2(float a, float b) {
    __half2 h = __floats2half2_rn(a, b);
    return *(uint32_t*)&h;
}

__device__ __forceinline__ void mma_f16(float* d, const uint32_t* a, const uint32_t* b) {
    asm volatile(
        "mma.sync.aligned.m16n8k16.row.col.f32.f16.f16.f32 "
        "{%0,%1,%2,%3},{%4,%5,%6,%7},{%8,%9},{%0,%1,%2,%3};"
        : "+f"(d[0]), "+f"(d[1]), "+f"(d[2]), "+f"(d[3])
        : "r"(a[0]), "r"(a[1]), "r"(a[2]), "r"(a[3]), "r"(b[0]), "r"(b[1]));
}

__device__ __forceinline__ void ldmatrix4(uint32_t* r, uint32_t addr) {
    asm volatile("ldmatrix.sync.aligned.m8n8.x4.shared.b16 {%0,%1,%2,%3}, [%4];"
                 : "=r"(r[0]), "=r"(r[1]), "=r"(r[2]), "=r"(r[3]) : "r"(addr));
}

__device__ __forceinline__ void cp_async16(uint32_t* dst_smem, const uint32_t* src_gmem) {
    uint32_t s = (uint32_t)__cvta_generic_to_shared(dst_smem);
    asm volatile("cp.async.cg.shared.global [%0], [%1], 16;\n" :: "r"(s), "l"(src_gmem));
}

// ===========================================================================
// MAIN GEMM: 128(M) x 256(N) CTA, 256 threads, 3-stage pipeline, ldmatrix.
// Smem stage = [128 A-rows | 256 B-rows] x PITCH words (K-tile = 64 fp16).
// ===========================================================================
#define BMm      128
#define BNm      256
#define SROWS    (BMm + BNm)              // 384 rows per stage
#define STG_W    (SROWS * PITCH)          // words per stage
#define NSTAGE   3

template<bool FUSE, bool BIASF>
__global__ void __launch_bounds__(256, 1)
gemm_main(const uint32_t* __restrict__ X,      // [M][2048] pairs
          const uint32_t* __restrict__ Wt,     // [N][2048] pairs
          const uint32_t* __restrict__ ZS,     // [M][32] pairs (FUSE)
          const uint32_t* __restrict__ BL,     // [N][32] pairs (FUSE)
          const float* __restrict__ bias,
          float* __restrict__ out,
          int KT_main, int KT_total)
{
    extern __shared__ uint32_t smem[];

    const int tid  = threadIdx.x;
    const int lane = tid & 31;
    const int wid  = tid >> 5;
    const int wm   = wid >> 2;     // 0..1  -> m offset 64
    const int wn   = wid & 3;      // 0..3  -> n offset 64

    const int bm = blockIdx.y * BMm;
    const int bn = blockIdx.x * BNm;

    // ldmatrix lane->address decomposition
    const int la_row = (lane & 7) + ((lane >> 3) & 1) * 8;  // A: mat&1 -> +8 rows
    const int la_kp  = (lane >> 4) * 4;                     // A: mat>>1 -> +4 pairs
    const int lb_row = (lane & 7) + (lane >> 4) * 8;        // B: mat>>1 -> +8 rows
    const int lb_kp  = ((lane >> 3) & 1) * 4;               // B: mat&1 -> +4 pairs

    const uint32_t smem_u = (uint32_t)__cvta_generic_to_shared(smem);
    const uint32_t a_base = smem_u + 4u * ((uint32_t)(wm * 64 + la_row) * PITCH + la_kp);
    const uint32_t b_base = smem_u + 4u * ((uint32_t)(BMm + wn * 64 + lb_row) * PITCH + lb_kp);

    float acc[4][8][4];
#pragma unroll
    for (int mt = 0; mt < 4; mt++)
#pragma unroll
        for (int nt = 0; nt < 8; nt++)
#pragma unroll
            for (int i = 0; i < 4; i++) acc[mt][nt][i] = 0.0f;

    auto issue_copy = [&](int kb, int stage) {
        uint32_t* sp = smem + stage * STG_W;
        const bool main_k = (!FUSE) || (kb < KT_main);
        // A tile: 128 rows x 8 uint4  -> 1024 uint4, 4 iters
#pragma unroll
        for (int i = 0; i < 4; i++) {
            int linear = tid + i * 256;
            int row = linear >> 3;
            int cv  = (linear & 7) << 2;
            const uint32_t* src = main_k
                ? X  + (size_t)(bm + row) * D_IN_P + (size_t)kb * 32 + cv
                : ZS + (size_t)(bm + row) * R_P + cv;
            cp_async16(&sp[row * PITCH + cv], src);
        }
        // B tile: 256 rows x 8 uint4 -> 2048 uint4, 8 iters
#pragma unroll
        for (int i = 0; i < 8; i++) {
            int linear = tid + i * 256;
            int row = linear >> 3;
            int cv  = (linear & 7) << 2;
            const uint32_t* src = main_k
                ? Wt + (size_t)(bn + row) * D_IN_P + (size_t)kb * 32 + cv
                : BL + (size_t)(bn + row) * R_P + cv;
            cp_async16(&sp[(BMm + row) * PITCH + cv], src);
        }
        asm volatile("cp.async.commit_group;\n" ::: "memory");
    };

    issue_copy(0, 0);
    if (KT_total > 1) issue_copy(1, 1);

    for (int kb = 0; kb < KT_total; kb++) {
        const int s = kb % NSTAGE;
        if (kb + 1 < KT_total)
            asm volatile("cp.async.wait_group 1;\n" ::: "memory");
        else
            asm volatile("cp.async.wait_group 0;\n" ::: "memory");
        __syncthreads();

        if (kb + 2 < KT_total) issue_copy(kb + 2, (kb + 2) % NSTAGE);

        const uint32_t sa = a_base + 4u * (uint32_t)(s * STG_W);
        const uint32_t sb = b_base + 4u * (uint32_t)(s * STG_W);

#pragma unroll
        for (int kk = 0; kk < 4; kk++) {
            uint32_t afrag[4][4];
#pragma unroll
            for (int mt = 0; mt < 4; mt++)
                ldmatrix4(afrag[mt], sa + 4u * (uint32_t)(mt * 16 * PITCH + kk * 8));
            uint32_t bfrag[8][2];
#pragma unroll
            for (int np = 0; np < 4; np++) {
                uint32_t r[4];
                ldmatrix4(r, sb + 4u * (uint32_t)(np * 16 * PITCH + kk * 8));
                bfrag[np * 2 + 0][0] = r[0];
                bfrag[np * 2 + 0][1] = r[1];
                bfrag[np * 2 + 1][0] = r[2];
                bfrag[np * 2 + 1][1] = r[3];
            }
#pragma unroll
            for (int mt = 0; mt < 4; mt++)
#pragma unroll
                for (int nt = 0; nt < 8; nt++)
                    mma_f16(acc[mt][nt], afrag[mt], bfrag[nt]);
        }
    }

    // Epilogue
#pragma unroll
    for (int mt = 0; mt < 4; mt++) {
#pragma unroll
        for (int nt = 0; nt < 8; nt++) {
            int r0 = bm + wm * 64 + mt * 16 + (lane >> 2);
            int c0 = bn + wn * 64 + nt * 8 + (lane & 3) * 2;
            float b0 = 0.0f, b1 = 0.0f;
            if (BIASF) { b0 = __ldg(&bias[c0]); b1 = __ldg(&bias[c0 + 1]); }
            float2 v0 = make_float2(acc[mt][nt][0] + b0, acc[mt][nt][1] + b1);
            float2 v1 = make_float2(acc[mt][nt][2] + b0, acc[mt][nt][3] + b1);
            *(float2*)&out[(size_t)r0 * N_FIX + c0]       = v0;
            *(float2*)&out[(size_t)(r0 + 8) * N_FIX + c0] = v1;
        }
    }
}

// ===========================================================================
// Z-GEMM (proven R11 path): 64x64 CTA, 4 warps, scalar-LDS fragments.
// ===========================================================================
template<int BM, int BN>
__global__ void __launch_bounds__(128)
gemm_z(const uint32_t* __restrict__ X,  int ldx,
       const uint32_t* __restrict__ Wt, int ldw,
       float* __restrict__ out, int ldo, int KT_total)
{
    constexpr int MT = BM / 32;
    constexpr int NT = BN / 16;
    extern __shared__ uint32_t smem[];
    uint32_t* As = smem;
    uint32_t* Bs = smem + 2 * BM * PITCH;

    const int tid  = threadIdx.x;
    const int lane = tid & 31;
    const int wid  = tid >> 5;
    const int wm   = wid >> 1;
    const int wn   = wid & 1;

    const int bm = blockIdx.y * BM;
    const int bn = blockIdx.x * BN;

    float acc[MT][NT][4];
#pragma unroll
    for (int mt = 0; mt < MT; mt++)
#pragma unroll
        for (int nt = 0; nt < NT; nt++)
#pragma unroll
            for (int i = 0; i < 4; i++) acc[mt][nt][i] = 0.0f;

    auto issue_copy = [&](int kb, int stage) {
        uint32_t* as = As + stage * BM * PITCH;
        uint32_t* bs = Bs + stage * BN * PITCH;
#pragma unroll
        for (int i = 0; i < BM / 16; i++) {
            int linear = tid + i * 128;
            int row = linear >> 3;
            int cv  = (linear & 7) << 2;
            cp_async16(&as[row * PITCH + cv],
                       X + (size_t)(bm + row) * ldx + (size_t)kb * 32 + cv);
        }
#pragma unroll
        for (int i = 0; i < BN / 16; i++) {
            int linear = tid + i * 128;
            int row = linear >> 3;
            int cv  = (linear & 7) << 2;
            cp_async16(&bs[row * PITCH + cv],
                       Wt + (size_t)(bn + row) * ldw + (size_t)kb * 32 + cv);
        }
        asm volatile("cp.async.commit_group;\n" ::: "memory");
    };

    issue_copy(0, 0);

    for (int kb = 0; kb < KT_total; kb++) {
        const int stage = kb & 1;
        if (kb + 1 < KT_total) {
            issue_copy(kb + 1, (kb + 1) & 1);
            asm volatile("cp.async.wait_group 1;\n" ::: "memory");
        } else {
            asm volatile("cp.async.wait_group 0;\n" ::: "memory");
        }
        __syncthreads();

        const uint32_t* as = As + stage * BM * PITCH + (wm * (BM / 2)) * PITCH;
        const uint32_t* bs = Bs + stage * BN * PITCH + (wn * (BN / 2)) * PITCH;

#pragma unroll
        for (int kk = 0; kk < 4; kk++) {
            uint32_t afrag[MT][4];
#pragma unroll
            for (int mt = 0; mt < MT; mt++) {
                int r = mt * 16 + (lane >> 2);
                int c = kk * 8 + (lane & 3);
                afrag[mt][0] = as[r * PITCH + c];
                afrag[mt][1] = as[(r + 8) * PITCH + c];
                afrag[mt][2] = as[r * PITCH + c + 4];
                afrag[mt][3] = as[(r + 8) * PITCH + c + 4];
            }
            uint32_t bfrag[NT][2];
#pragma unroll
            for (int nt = 0; nt < NT; nt++) {
                int n = nt * 8 + (lane >> 2);
                int c = kk * 8 + (lane & 3);
                bfrag[nt][0] = bs[n * PITCH + c];
                bfrag[nt][1] = bs[n * PITCH + c + 4];
            }
#pragma unroll
            for (int mt = 0; mt < MT; mt++)
#pragma unroll
                for (int nt = 0; nt < NT; nt++)
                    mma_f16(acc[mt][nt], afrag[mt], bfrag[nt]);
        }
        __syncthreads();
    }

#pragma unroll
    for (int mt = 0; mt < MT; mt++) {
#pragma unroll
        for (int nt = 0; nt < NT; nt++) {
            int r0 = bm + wm * (BM / 2) + mt * 16 + (lane >> 2);
            int c0 = bn + wn * (BN / 2) + nt * 8 + (lane & 3) * 2;
            float2 v0 = make_float2(acc[mt][nt][0], acc[mt][nt][1]);
            float2 v1 = make_float2(acc[mt][nt][2], acc[mt][nt][3]);
            *(float2*)&out[(size_t)r0 * ldo + c0]       = v0;
            *(float2*)&out[(size_t)(r0 + 8) * ldo + c0] = v1;
        }
    }
}

// ---------------------------------------------------------------------------
__global__ void cvt_f16_kernel(const float4* __restrict__ in,
                               uint2* __restrict__ out, int n4)
{
    int i = blockIdx.x * blockDim.x + threadIdx.x;
    const int stride = gridDim.x * blockDim.x;
    for (; i < n4; i += stride) {
        float4 v = in[i];
        uint2 o;
        o.x = pack2(v.x, v.y);
        o.y = pack2(v.z, v.w);
        out[i] = o;
    }
}

// ---------------------------------------------------------------------------
__global__ void topk_mask_kernel(const float* __restrict__ z,
                                 __half* __restrict__ zsh, int M)
{
    const int row  = blockIdx.x * 8 + (threadIdx.x >> 5);
    const int lane = threadIdx.x & 31;
    if (row >= M) return;

    float z0 = z[row * R_C + lane];
    float z1 = z[row * R_C + lane + 32];
    float v0 = fabsf(z0), v1 = fabsf(z1);
    bool a0 = true, a1 = true;
    float thr = 0.0f;

#pragma unroll 1
    for (int it = 0; it < KSEL_C; it++) {
        float m = fmaxf(a0 ? v0 : -1.0f, a1 ? v1 : -1.0f);
#pragma unroll
        for (int off = 16; off; off >>= 1)
            m = fmaxf(m, __shfl_xor_sync(0xffffffffu, m, off));
        thr = m;
        unsigned b = __ballot_sync(0xffffffffu, a0 && v0 == m);
        if (b) {
            if (lane == (__ffs(b) - 1)) a0 = false;
        } else {
            unsigned b2 = __ballot_sync(0xffffffffu, a1 && v1 == m);
            if (lane == (__ffs(b2) - 1)) a1 = false;
        }
    }

    const float inv_t = 1.0f / TEMP_C;
    float m0 = 1.0f / (1.0f + expf(-(v0 - thr) * inv_t));
    float m1 = 1.0f / (1.0f + expf(-(v1 - thr) * inv_t));
    zsh[row * R_C + lane]      = __float2half_rn(z0 * m0);
    zsh[row * R_C + lane + 32] = __float2half_rn(z1 * m1);
}

// ---------------------------------------------------------------------------
extern "C" void kernel_launch(void* const* d_in, const int* in_sizes, int n_in,
                              void* d_out, int out_size)
{
    const float* x    = (const float*)d_in[0];
    const float* Amat = (const float*)d_in[1];
    const float* Bmat = (const float*)d_in[2];
    const float* Wmat = (const float*)d_in[3];
    const float* bias = (const float*)d_in[4];
    float* out = (float*)d_out;

    const int M = in_sizes[0] / D_IN_C;          // 8192
    const int N = in_sizes[4];                   // 4096

    uint32_t *xh, *wh, *ah, *bh, *zsh;
    float* zptr;
    cudaGetSymbolAddress((void**)&xh,   g_xh);
    cudaGetSymbolAddress((void**)&wh,   g_wh);
    cudaGetSymbolAddress((void**)&ah,   g_ah);
    cudaGetSymbolAddress((void**)&bh,   g_bh);
    cudaGetSymbolAddress((void**)&zsh,  g_zsh);
    cudaGetSymbolAddress((void**)&zptr, g_z);

    // 0) pre-convert operands to fp16 pairs
    cvt_f16_kernel<<<1024, 256>>>((const float4*)x,    (uint2*)xh, M * D_IN_C / 4);
    cvt_f16_kernel<<<1024, 256>>>((const float4*)Wmat, (uint2*)wh, N * D_IN_C / 4);
    cvt_f16_kernel<<<256,  256>>>((const float4*)Amat, (uint2*)ah, R_C * D_IN_C / 4);
    cvt_f16_kernel<<<256,  256>>>((const float4*)Bmat, (uint2*)bh, N * R_C / 4);

    constexpr int SMEM_MAIN = NSTAGE * STG_W * 4;          // 165888 B
    constexpr int SMEM_Z    = 2 * (64 + 64) * PITCH * 4;   // 36864 B
    cudaFuncSetAttribute(gemm_main<true, true>,
                         cudaFuncAttributeMaxDynamicSharedMemorySize, SMEM_MAIN);
    cudaFuncSetAttribute(gemm_z<64, 64>,
                         cudaFuncAttributeMaxDynamicSharedMemorySize, SMEM_Z);

    // 1) z = x @ A^T   (M x 64, K = 4096)
    {
        dim3 grid(1, M / 64);
        gemm_z<64, 64><<<grid, 128, SMEM_Z>>>(
            xh, D_IN_P, ah, D_IN_P, zptr, R_C, D_IN_C / 64);
    }

    // 2) soft top-k mask -> z_sparse (fp16)
    topk_mask_kernel<<<M / 8, 256>>>(zptr, (__half*)zsh, M);

    // 3) out = x @ W^T + bias + z_sparse @ B^T   (LoRA = one extra K-tile)
    {
        dim3 grid(N / BNm, M / BMm);
        gemm_main<true, true><<<grid, 256, SMEM_MAIN>>>(
            xh, wh, zsh, bh, bias, out,
            D_IN_C / 64, D_IN_C / 64 + 1);
    }
}